// round 1
// baseline (speedup 1.0000x reference)
#include <cuda_runtime.h>

#define NCELLS_TOTAL 802816      // 16384 * 49
#define CELLS_PER_BLOCK 256
#define NTHREADS 256
#define NBLOCKS (NCELLS_TOTAL / CELLS_PER_BLOCK)   // 3136
#define ELE 30
#define CSTRIDE 33               // padded floats per cell in smem (33 mod 32 == 1 -> conflict-free)
#define F4_PER_TENSOR (CELLS_PER_BLOCK * ELE / 4)  // 1920

__device__ float g_partials[NBLOCKS];

__device__ __forceinline__ float iou_fn(const float* bp, const float* bt) {
    // boxes are (cx, cy, w, h); corners; clipped intersection; same formula as reference
    float px1 = bp[0] - bp[2] * 0.5f, py1 = bp[1] - bp[3] * 0.5f;
    float px2 = bp[0] + bp[2] * 0.5f, py2 = bp[1] + bp[3] * 0.5f;
    float tx1 = bt[0] - bt[2] * 0.5f, ty1 = bt[1] - bt[3] * 0.5f;
    float tx2 = bt[0] + bt[2] * 0.5f, ty2 = bt[1] + bt[3] * 0.5f;
    float lx = fmaxf(px1, tx1), ly = fmaxf(py1, ty1);
    float rx = fminf(px2, tx2), ry = fminf(py2, ty2);
    float w = fmaxf(rx - lx, 0.0f);
    float h = fmaxf(ry - ly, 0.0f);
    float inter = w * h;
    float ap = (px2 - px1) * (py2 - py1);
    float at = (tx2 - tx1) * (ty2 - ty1);
    return inter / (ap + at - inter + 1e-10f);
}

__global__ __launch_bounds__(NTHREADS)
void yolo_loss_kernel(const float* __restrict__ predict,
                      const float* __restrict__ target) {
    extern __shared__ float smem[];
    float* sp = smem;                                  // [CELLS_PER_BLOCK * CSTRIDE]
    float* st = smem + CELLS_PER_BLOCK * CSTRIDE;

    const int tid = threadIdx.x;
    const int blockF4 = blockIdx.x * F4_PER_TENSOR;
    const float4* p4 = (const float4*)predict;
    const float4* t4 = (const float4*)target;

    // Coalesced float4 load of this block's 256 cells, scatter to padded smem.
    for (int i = tid; i < F4_PER_TENSOR; i += NTHREADS) {
        float4 vp = p4[blockF4 + i];
        float4 vt = t4[blockF4 + i];
        int L = i * 4;
        const float* fp = (const float*)&vp;
        const float* ft = (const float*)&vt;
        #pragma unroll
        for (int k = 0; k < 4; k++) {
            int Lk = L + k;
            int cell = Lk / ELE;
            int e = Lk - cell * ELE;
            sp[cell * CSTRIDE + e] = fp[k];
            st[cell * CSTRIDE + e] = ft[k];
        }
    }
    __syncthreads();

    // One thread per cell.
    const float* P = sp + tid * CSTRIDE;
    const float* T = st + tid * CSTRIDE;

    float p[10], t[10];
    #pragma unroll
    for (int k = 0; k < 10; k++) { p[k] = P[k]; t[k] = T[k]; }

    float conf_flag = t[5];
    float coord = (conf_flag > 0.0f) ? 1.0f : 0.0f;
    float noobj = (conf_flag == 0.0f) ? 1.0f : 0.0f;

    float d4a = p[4] - t[4];
    float d4b = p[9] - t[9];
    float noobj_conf = noobj * (d4a * d4a + d4b * d4b);

    // pairwise IoU: iou[pred_box][target_box]
    float iou00 = iou_fn(p,     t);
    float iou01 = iou_fn(p,     t + 5);
    float iou10 = iou_fn(p + 5, t);
    float iou11 = iou_fn(p + 5, t + 5);

    // argmax over pred axis, ties -> index 0 (matches jnp.argmax)
    int bi0 = (iou10 > iou00) ? 1 : 0;
    int bi1 = (iou11 > iou01) ? 1 : 0;
    float best0 = (bi0 == 0 || bi1 == 0) ? 1.0f : 0.0f;
    float best1 = (bi0 == 1 || bi1 == 1) ? 1.0f : 0.0f;
    float resp0 = coord * best0;
    float resp1 = coord * best1;

    float conf_loss = resp0 * d4a * d4a + resp1 * d4b * d4b;

    float c0 = p[0] - t[0], c1 = p[1] - t[1];
    float c5 = p[5] - t[5], c6 = p[6] - t[6];
    float center = resp0 * (c0 * c0 + c1 * c1) + resp1 * (c5 * c5 + c6 * c6);

    float w0 = p[2] - t[2], h0 = p[3] - t[3];
    float w1 = p[7] - t[7], h1 = p[8] - t[8];
    float wh = resp0 * (w0 * w0 + h0 * h0) + resp1 * (w1 * w1 + h1 * h1);

    float cls = 0.0f;
    #pragma unroll
    for (int e = 10; e < ELE; e++) {
        float d = P[e] - T[e];
        cls += d * d;
    }
    cls *= coord;

    float total = 5.0f * (center + wh) + conf_loss + 0.5f * noobj_conf + cls;

    // block reduction (deterministic)
    #pragma unroll
    for (int o = 16; o > 0; o >>= 1)
        total += __shfl_xor_sync(0xFFFFFFFFu, total, o);

    __shared__ float wsum[NTHREADS / 32];
    if ((tid & 31) == 0) wsum[tid >> 5] = total;
    __syncthreads();
    if (tid < NTHREADS / 32) {
        float s = wsum[tid];
        #pragma unroll
        for (int o = (NTHREADS / 32) / 2; o > 0; o >>= 1)
            s += __shfl_xor_sync((1u << (NTHREADS / 32)) - 1u, s, o);
        if (tid == 0) g_partials[blockIdx.x] = s;
    }
}

__global__ __launch_bounds__(1024)
void final_reduce_kernel(float* __restrict__ out, int out_size) {
    const int tid = threadIdx.x;
    float s = 0.0f;
    for (int i = tid; i < NBLOCKS; i += 1024) s += g_partials[i];

    #pragma unroll
    for (int o = 16; o > 0; o >>= 1)
        s += __shfl_xor_sync(0xFFFFFFFFu, s, o);

    __shared__ float wsum[32];
    if ((tid & 31) == 0) wsum[tid >> 5] = s;
    __syncthreads();
    if (tid < 32) {
        float v = wsum[tid];
        #pragma unroll
        for (int o = 16; o > 0; o >>= 1)
            v += __shfl_xor_sync(0xFFFFFFFFu, v, o);
        if (tid == 0) out[0] = v;
    }
    // clear any extra output elements (d_out is poisoned)
    for (int i = 1024 + tid; i < out_size; i += 1024) out[i] = 0.0f;
    if (tid > 0 && tid < out_size && tid < 1024) out[tid] = 0.0f;
}

extern "C" void kernel_launch(void* const* d_in, const int* in_sizes, int n_in,
                              void* d_out, int out_size) {
    const float* predict = (const float*)d_in[0];
    const float* target  = (const float*)d_in[1];
    float* out = (float*)d_out;

    size_t smem = (size_t)2 * CELLS_PER_BLOCK * CSTRIDE * sizeof(float);  // 67584 B
    cudaFuncSetAttribute(yolo_loss_kernel,
                         cudaFuncAttributeMaxDynamicSharedMemorySize, (int)smem);

    yolo_loss_kernel<<<NBLOCKS, NTHREADS, smem>>>(predict, target);
    final_reduce_kernel<<<1, 1024>>>(out, out_size);
}

// round 2
// speedup vs baseline: 1.2209x; 1.2209x over previous
#include <cuda_runtime.h>

#define NCELLS_TOTAL 802816      // 16384 * 49
#define CELLS_PER_TILE 256
#define NTHREADS 256
#define NTILES (NCELLS_TOTAL / CELLS_PER_TILE)     // 3136
#define GRID 444                                   // 148 SMs * 3 blocks (persistent)
#define ELE 30
#define F4_PER_TILE (CELLS_PER_TILE * ELE / 4)     // 1920 float4 per tensor per tile

__device__ float g_partials[GRID];
__device__ unsigned int g_count = 0;

__device__ __forceinline__ float iou_fn(const float* bp, const float* bt) {
    float px1 = bp[0] - bp[2] * 0.5f, py1 = bp[1] - bp[3] * 0.5f;
    float px2 = bp[0] + bp[2] * 0.5f, py2 = bp[1] + bp[3] * 0.5f;
    float tx1 = bt[0] - bt[2] * 0.5f, ty1 = bt[1] - bt[3] * 0.5f;
    float tx2 = bt[0] + bt[2] * 0.5f, ty2 = bt[1] + bt[3] * 0.5f;
    float lx = fmaxf(px1, tx1), ly = fmaxf(py1, ty1);
    float rx = fminf(px2, tx2), ry = fminf(py2, ty2);
    float w = fmaxf(rx - lx, 0.0f);
    float h = fmaxf(ry - ly, 0.0f);
    float inter = w * h;
    float ap = (px2 - px1) * (py2 - py1);
    float at = (tx2 - tx1) * (ty2 - ty1);
    return inter / (ap + at - inter + 1e-10f);
}

__device__ __forceinline__ float block_reduce(float v, float* wsum) {
    const int tid = threadIdx.x;
    #pragma unroll
    for (int o = 16; o > 0; o >>= 1)
        v += __shfl_xor_sync(0xFFFFFFFFu, v, o);
    if ((tid & 31) == 0) wsum[tid >> 5] = v;
    __syncthreads();
    v = 0.0f;
    if (tid < 32) {
        v = (tid < NTHREADS / 32) ? wsum[tid] : 0.0f;
        #pragma unroll
        for (int o = 4; o > 0; o >>= 1)
            v += __shfl_xor_sync(0xFFFFFFFFu, v, o);
    }
    return v;  // valid in tid 0
}

__global__ __launch_bounds__(NTHREADS)
void yolo_loss_kernel(const float* __restrict__ predict,
                      const float* __restrict__ target,
                      float* __restrict__ out, int out_size) {
    extern __shared__ float smem[];
    float* sp = smem;                         // [7680] floats, linear
    float* st = smem + CELLS_PER_TILE * ELE;  // [7680] floats, linear
    __shared__ float wsum[NTHREADS / 32];
    __shared__ int s_is_last;

    const int tid = threadIdx.x;
    const float4* p4 = (const float4*)predict;
    const float4* t4 = (const float4*)target;
    float4* sp4 = (float4*)sp;
    float4* st4 = (float4*)st;

    float acc = 0.0f;

    for (int tile = blockIdx.x; tile < NTILES; tile += GRID) {
        const int base = tile * F4_PER_TILE;

        __syncthreads();  // previous tile's smem reads complete

        // Batched, fully-coalesced float4 loads -> registers (high MLP), then
        // linear STS.128 (no index math, conflict-free).
        float4 rp[8], rt[8];
        #pragma unroll
        for (int k = 0; k < 8; k++) {
            int i = tid + k * NTHREADS;
            if (i < F4_PER_TILE) {
                rp[k] = p4[base + i];
                rt[k] = t4[base + i];
            }
        }
        #pragma unroll
        for (int k = 0; k < 8; k++) {
            int i = tid + k * NTHREADS;
            if (i < F4_PER_TILE) {
                sp4[i] = rp[k];
                st4[i] = rt[k];
            }
        }
        __syncthreads();

        // One thread per cell. Stride-30 float2 reads are bank-conflict-free.
        const float2* P2 = ((const float2*)sp) + tid * (ELE / 2);
        const float2* T2 = ((const float2*)st) + tid * (ELE / 2);

        float p[10], t[10];
        #pragma unroll
        for (int j = 0; j < 5; j++) {
            float2 a = P2[j]; p[2 * j] = a.x; p[2 * j + 1] = a.y;
            float2 b = T2[j]; t[2 * j] = b.x; t[2 * j + 1] = b.y;
        }

        float conf_flag = t[5];
        float coord = (conf_flag > 0.0f) ? 1.0f : 0.0f;
        float noobj = (conf_flag == 0.0f) ? 1.0f : 0.0f;

        float d4a = p[4] - t[4];
        float d4b = p[9] - t[9];
        float noobj_conf = noobj * (d4a * d4a + d4b * d4b);

        float iou00 = iou_fn(p,     t);
        float iou01 = iou_fn(p,     t + 5);
        float iou10 = iou_fn(p + 5, t);
        float iou11 = iou_fn(p + 5, t + 5);

        // argmax over predictor axis, ties -> index 0 (matches jnp.argmax)
        int bi0 = (iou10 > iou00) ? 1 : 0;
        int bi1 = (iou11 > iou01) ? 1 : 0;
        float best0 = (bi0 == 0 || bi1 == 0) ? 1.0f : 0.0f;
        float best1 = (bi0 == 1 || bi1 == 1) ? 1.0f : 0.0f;
        float resp0 = coord * best0;
        float resp1 = coord * best1;

        float conf_loss = resp0 * d4a * d4a + resp1 * d4b * d4b;

        float c0 = p[0] - t[0], c1 = p[1] - t[1];
        float c5 = p[5] - t[5], c6 = p[6] - t[6];
        float center = resp0 * (c0 * c0 + c1 * c1) + resp1 * (c5 * c5 + c6 * c6);

        float w0 = p[2] - t[2], h0 = p[3] - t[3];
        float w1 = p[7] - t[7], h1 = p[8] - t[8];
        float wh = resp0 * (w0 * w0 + h0 * h0) + resp1 * (w1 * w1 + h1 * h1);

        float cls = 0.0f;
        #pragma unroll
        for (int j = 5; j < 15; j++) {
            float2 a = P2[j];
            float2 b = T2[j];
            float dx = a.x - b.x;
            float dy = a.y - b.y;
            cls += dx * dx + dy * dy;
        }
        cls *= coord;

        acc += 5.0f * (center + wh) + conf_loss + 0.5f * noobj_conf + cls;
    }

    // Per-block deterministic reduction
    __syncthreads();
    float bsum = block_reduce(acc, wsum);
    if (tid == 0) {
        g_partials[blockIdx.x] = bsum;
        __threadfence();
        unsigned int prev = atomicAdd(&g_count, 1u);
        s_is_last = (prev == GRID - 1) ? 1 : 0;
    }
    __syncthreads();

    if (s_is_last) {
        __threadfence();
        // Deterministic final sum of 444 partials
        float s = g_partials[tid];
        if (tid + NTHREADS < GRID) s += g_partials[tid + NTHREADS];
        __syncthreads();  // reuse wsum safely
        float tot = block_reduce(s, wsum);
        if (tid == 0) {
            out[0] = tot;
            g_count = 0;  // reset for next (graph-replayed) launch
        }
        // d_out is poisoned; zero any extra elements
        for (int i = tid + 1; i < out_size; i += NTHREADS) out[i] = 0.0f;
    }
}

extern "C" void kernel_launch(void* const* d_in, const int* in_sizes, int n_in,
                              void* d_out, int out_size) {
    const float* predict = (const float*)d_in[0];
    const float* target  = (const float*)d_in[1];
    float* out = (float*)d_out;

    size_t smem = (size_t)2 * CELLS_PER_TILE * ELE * sizeof(float);  // 61440 B
    cudaFuncSetAttribute(yolo_loss_kernel,
                         cudaFuncAttributeMaxDynamicSharedMemorySize, (int)smem);

    yolo_loss_kernel<<<GRID, NTHREADS, smem>>>(predict, target, out, out_size);
}

// round 3
// speedup vs baseline: 1.3766x; 1.1275x over previous
#include <cuda_runtime.h>
#include <cstdint>

#define NCELLS_TOTAL 802816              // 16384 * 49
#define CELLS_PER_TILE 128
#define NTHREADS 256
#define NTILES (NCELLS_TOTAL / CELLS_PER_TILE)   // 6272
#define GRID 296                                  // 148 SMs * 2 blocks, persistent
#define ELE 30
#define F4_PER_TENSOR (CELLS_PER_TILE * ELE / 4)  // 960
#define TILE_FLOATS (CELLS_PER_TILE * ELE)        // 3840
#define BUF_FLOATS (2 * TILE_FLOATS)              // 7680 floats per stage (p + t)

__device__ float g_partials[GRID];
__device__ unsigned int g_count = 0;

__device__ __forceinline__ float iou_fn(const float* bp, const float* bt) {
    float px1 = bp[0] - bp[2] * 0.5f, py1 = bp[1] - bp[3] * 0.5f;
    float px2 = bp[0] + bp[2] * 0.5f, py2 = bp[1] + bp[3] * 0.5f;
    float tx1 = bt[0] - bt[2] * 0.5f, ty1 = bt[1] - bt[3] * 0.5f;
    float tx2 = bt[0] + bt[2] * 0.5f, ty2 = bt[1] + bt[3] * 0.5f;
    float lx = fmaxf(px1, tx1), ly = fmaxf(py1, ty1);
    float rx = fminf(px2, tx2), ry = fminf(py2, ty2);
    float w = fmaxf(rx - lx, 0.0f);
    float h = fmaxf(ry - ly, 0.0f);
    float inter = w * h;
    float ap = (px2 - px1) * (py2 - py1);
    float at = (tx2 - tx1) * (ty2 - ty1);
    return inter / (ap + at - inter + 1e-10f);
}

__device__ __forceinline__ float block_reduce(float v, float* wsum) {
    const int tid = threadIdx.x;
    #pragma unroll
    for (int o = 16; o > 0; o >>= 1)
        v += __shfl_xor_sync(0xFFFFFFFFu, v, o);
    if ((tid & 31) == 0) wsum[tid >> 5] = v;
    __syncthreads();
    v = 0.0f;
    if (tid < 32) {
        v = (tid < NTHREADS / 32) ? wsum[tid] : 0.0f;
        #pragma unroll
        for (int o = 4; o > 0; o >>= 1)
            v += __shfl_xor_sync(0xFFFFFFFFu, v, o);
    }
    return v;  // valid in tid 0
}

// Issue async copy of one tile (p + t) into `buf`, then commit a group.
// Always commits (even past the end) so group counts stay uniform.
__device__ __forceinline__ void prefetch_tile(int tile, float* buf,
                                              const float4* __restrict__ p4,
                                              const float4* __restrict__ t4,
                                              int tid) {
    if (tile < NTILES) {
        const int base = tile * F4_PER_TENSOR;
        uint32_t sP = (uint32_t)__cvta_generic_to_shared(buf);
        uint32_t sT = sP + TILE_FLOATS * 4;
        #pragma unroll
        for (int k = 0; k < 4; k++) {
            int i = tid + k * NTHREADS;
            if (i < F4_PER_TENSOR) {
                asm volatile("cp.async.cg.shared.global [%0], [%1], 16;"
                             :: "r"(sP + i * 16), "l"(p4 + base + i));
                asm volatile("cp.async.cg.shared.global [%0], [%1], 16;"
                             :: "r"(sT + i * 16), "l"(t4 + base + i));
            }
        }
    }
    asm volatile("cp.async.commit_group;");
}

__global__ __launch_bounds__(NTHREADS)
void yolo_loss_kernel(const float* __restrict__ predict,
                      const float* __restrict__ target,
                      float* __restrict__ out, int out_size) {
    extern __shared__ float smem[];   // [2 * BUF_FLOATS]
    __shared__ float wsum[NTHREADS / 32];
    __shared__ int s_is_last;

    const int tid = threadIdx.x;
    const float4* p4 = (const float4*)predict;
    const float4* t4 = (const float4*)target;

    float acc = 0.0f;

    // Prologue: prefetch first tile into stage 0
    prefetch_tile(blockIdx.x, smem, p4, t4, tid);

    int parity = 0;
    for (int tile = blockIdx.x; tile < NTILES; tile += GRID) {
        // Prefetch next tile into the other stage (safe: barrier at end of prev iter)
        prefetch_tile(tile + GRID, smem + (parity ^ 1) * BUF_FLOATS, p4, t4, tid);

        // Wait until the current tile's group is complete (<=1 pending)
        asm volatile("cp.async.wait_group 1;");
        __syncthreads();

        const float* bp = smem + parity * BUF_FLOATS;
        const float* bt = bp + TILE_FLOATS;

        if (tid < CELLS_PER_TILE) {
            // ---- box half: elements 0..9 of one cell ----
            const float2* P2 = (const float2*)(bp + tid * ELE);
            const float2* T2 = (const float2*)(bt + tid * ELE);
            float p[10], t[10];
            #pragma unroll
            for (int j = 0; j < 5; j++) {
                float2 a = P2[j]; p[2 * j] = a.x; p[2 * j + 1] = a.y;
                float2 b = T2[j]; t[2 * j] = b.x; t[2 * j + 1] = b.y;
            }

            float conf_flag = t[5];
            float coord = (conf_flag > 0.0f) ? 1.0f : 0.0f;
            float noobj = (conf_flag == 0.0f) ? 1.0f : 0.0f;

            float d4a = p[4] - t[4];
            float d4b = p[9] - t[9];
            float noobj_conf = noobj * (d4a * d4a + d4b * d4b);

            float iou00 = iou_fn(p,     t);
            float iou01 = iou_fn(p,     t + 5);
            float iou10 = iou_fn(p + 5, t);
            float iou11 = iou_fn(p + 5, t + 5);

            int bi0 = (iou10 > iou00) ? 1 : 0;   // ties -> 0, matches jnp.argmax
            int bi1 = (iou11 > iou01) ? 1 : 0;
            float best0 = (bi0 == 0 || bi1 == 0) ? 1.0f : 0.0f;
            float best1 = (bi0 == 1 || bi1 == 1) ? 1.0f : 0.0f;
            float resp0 = coord * best0;
            float resp1 = coord * best1;

            float conf_loss = resp0 * d4a * d4a + resp1 * d4b * d4b;

            float c0 = p[0] - t[0], c1 = p[1] - t[1];
            float c5 = p[5] - t[5], c6 = p[6] - t[6];
            float center = resp0 * (c0 * c0 + c1 * c1) + resp1 * (c5 * c5 + c6 * c6);

            float w0 = p[2] - t[2], h0 = p[3] - t[3];
            float w1 = p[7] - t[7], h1 = p[8] - t[8];
            float wh = resp0 * (w0 * w0 + h0 * h0) + resp1 * (w1 * w1 + h1 * h1);

            acc += 5.0f * (center + wh) + conf_loss + 0.5f * noobj_conf;
        } else {
            // ---- class half: elements 10..29 of one cell ----
            const int cell = tid - CELLS_PER_TILE;
            const float* base_p = bp + cell * ELE;
            const float* base_t = bt + cell * ELE;
            float conf_flag = base_t[5];
            float coord = (conf_flag > 0.0f) ? 1.0f : 0.0f;

            const float2* P2 = (const float2*)(base_p + 10);
            const float2* T2 = (const float2*)(base_t + 10);
            float cls = 0.0f;
            #pragma unroll
            for (int j = 0; j < 10; j++) {
                float2 a = P2[j];
                float2 b = T2[j];
                float dx = a.x - b.x;
                float dy = a.y - b.y;
                cls += dx * dx + dy * dy;
            }
            acc += coord * cls;
        }

        __syncthreads();   // all reads of this stage done before it's overwritten
        parity ^= 1;
    }

    // Per-block deterministic reduction, then last-block final sum
    __syncthreads();
    float bsum = block_reduce(acc, wsum);
    if (tid == 0) {
        g_partials[blockIdx.x] = bsum;
        __threadfence();
        unsigned int prev = atomicAdd(&g_count, 1u);
        s_is_last = (prev == GRID - 1) ? 1 : 0;
    }
    __syncthreads();

    if (s_is_last) {
        __threadfence();
        float s = g_partials[tid];
        if (tid + NTHREADS < GRID) s += g_partials[tid + NTHREADS];
        __syncthreads();
        float tot = block_reduce(s, wsum);
        if (tid == 0) {
            out[0] = tot;
            g_count = 0;   // reset for next graph replay
        }
        for (int i = tid + 1; i < out_size; i += NTHREADS) out[i] = 0.0f;
    }
}

extern "C" void kernel_launch(void* const* d_in, const int* in_sizes, int n_in,
                              void* d_out, int out_size) {
    const float* predict = (const float*)d_in[0];
    const float* target  = (const float*)d_in[1];
    float* out = (float*)d_out;

    size_t smem = (size_t)2 * BUF_FLOATS * sizeof(float);   // 61440 B
    cudaFuncSetAttribute(yolo_loss_kernel,
                         cudaFuncAttributeMaxDynamicSharedMemorySize, (int)smem);

    yolo_loss_kernel<<<GRID, NTHREADS, smem>>>(predict, target, out, out_size);
}